// round 15
// baseline (speedup 1.0000x reference)
#include <cuda_runtime.h>
#include <cuda_bf16.h>
#include <math.h>

// CGCNN forward, sm_100a. Round 15 submission (design == round 13/14, cosmetic
// diffs only to alter the source hash after repeated broker failures).
#define NN 50000
#define EE 800000
#define IN_F 92
#define ED_F 50
#define HH 64
#define LL 4
#define GG 512
#define BN_EPS 1e-5f
#define TP 72   /* bf16 tile pitch: 144B rows, conflict-free fragment LDS */

// ================= scratch (device globals; allocations forbidden) ==========
__device__ float          g_x[NN * HH];
__device__ __nv_bfloat16  g_x_h[NN * HH];
__device__ __nv_bfloat16  g_x_l[NN * HH];
__device__ __nv_bfloat16  g_ea_h[EE * HH];
__device__ __nv_bfloat16  g_ea_l[EE * HH];
__device__ __nv_bfloat16  g_wsn_h[LL * 3 * 8192];
__device__ __nv_bfloat16  g_wsn_l[LL * 3 * 8192];
__device__ __nv_bfloat16  g_wpe_h[4096];
__device__ __nv_bfloat16  g_wpe_l[4096];
__device__ float          g_xprojd[NN * 128];
__device__ float          g_xprojs[NN * 128];
__device__ float          g_agg[NN * HH];
__device__ double         g_stats[128];
__device__ float          g_y[NN * HH];
__device__ float          g_pool[GG * HH];
__device__ float          g_cnt[GG];

// ================= helpers ===================================================
__device__ __forceinline__ float softplus_f(float x) {
    return fmaxf(x, 0.f) + __logf(1.f + __expf(-fabsf(x)));
}
__device__ __forceinline__ float sigmoid_f(float x) {
    return __fdividef(1.f, 1.f + __expf(-x));
}
__device__ __forceinline__ float msg_f(float S, float C) {
    return softplus_f(S) * sigmoid_f(C);
}
__device__ __forceinline__ void split_bf16(float v, __nv_bfloat16& h, __nv_bfloat16& l) {
    h = __float2bfloat16(v);
    l = __float2bfloat16(v - __bfloat162float(h));
}
__device__ __forceinline__ void mma_bf16(float c[4], const unsigned a[4], const unsigned b[2]) {
    asm volatile(
        "mma.sync.aligned.m16n8k16.row.col.f32.bf16.bf16.f32 "
        "{%0,%1,%2,%3}, {%4,%5,%6,%7}, {%8,%9}, {%0,%1,%2,%3};"
        : "+f"(c[0]), "+f"(c[1]), "+f"(c[2]), "+f"(c[3])
        : "r"(a[0]), "r"(a[1]), "r"(a[2]), "r"(a[3]), "r"(b[0]), "r"(b[1]));
}

// ================= fp32 embed: [rows,K]@[K,64] + bias + relu =================
template <int K, int KP, bool EMIT>
__global__ __launch_bounds__(256) void embed_kernel(
    const float* __restrict__ A, const float* __restrict__ W,
    const float* __restrict__ bias, float* __restrict__ out, int nrows)
{
    __shared__ float As[64 * KP];
    __shared__ float Bs[K * 64];
    const int r0 = blockIdx.x * 64;
    const int tid = threadIdx.x;

    for (int i = tid; i < 64 * K; i += 256) {
        int r = i / K, k = i - r * K;
        int gr = r0 + r;
        As[r * KP + k] = (gr < nrows) ? A[(size_t)gr * K + k] : 0.f;
    }
    for (int i = tid; i < K * 64; i += 256) Bs[i] = W[i];
    __syncthreads();

    const int rx = tid >> 4, cx = tid & 15;
    float acc[4][4];
#pragma unroll
    for (int i = 0; i < 4; i++)
#pragma unroll
        for (int j = 0; j < 4; j++) acc[i][j] = 0.f;

#pragma unroll 4
    for (int k = 0; k < K; k++) {
        float4 b = *(const float4*)&Bs[k * 64 + cx * 4];
#pragma unroll
        for (int i = 0; i < 4; i++) {
            float a = As[(rx * 4 + i) * KP + k];
            acc[i][0] += a * b.x; acc[i][1] += a * b.y;
            acc[i][2] += a * b.z; acc[i][3] += a * b.w;
        }
    }
    float4 bb = *(const float4*)&bias[cx * 4];
#pragma unroll
    for (int i = 0; i < 4; i++) {
        int gr = r0 + rx * 4 + i;
        if (gr < nrows) {
            float4 v;
            v.x = fmaxf(acc[i][0] + bb.x, 0.f);
            v.y = fmaxf(acc[i][1] + bb.y, 0.f);
            v.z = fmaxf(acc[i][2] + bb.z, 0.f);
            v.w = fmaxf(acc[i][3] + bb.w, 0.f);
            size_t base = (size_t)gr * 64 + cx * 4;
            *(float4*)&out[base] = v;
            if (EMIT) {
                __nv_bfloat16 h0, l0, h1, l1, h2, l2, h3, l3;
                split_bf16(v.x, h0, l0); split_bf16(v.y, h1, l1);
                split_bf16(v.z, h2, l2); split_bf16(v.w, h3, l3);
                *(__nv_bfloat162*)&g_x_h[base]     = __halves2bfloat162(h0, h1);
                *(__nv_bfloat162*)&g_x_h[base + 2] = __halves2bfloat162(h2, h3);
                *(__nv_bfloat162*)&g_x_l[base]     = __halves2bfloat162(l0, l1);
                *(__nv_bfloat162*)&g_x_l[base + 2] = __halves2bfloat162(l2, l3);
            }
        }
    }
}

// ================= weight split planes (once) ================================
__global__ void prep_wsplit_kernel(const float* __restrict__ smw,
                                   const float* __restrict__ cvw,
                                   const float* __restrict__ pew)
{
    int idx = blockIdx.x * 256 + threadIdx.x;
    if (idx < LL * 3 * 8192) {
        int l = idx / (3 * 8192);
        int rem = idx - l * 3 * 8192;
        int p = rem >> 13;
        int r = rem & 8191;
        int n = r >> 6, k = r & 63;
        const float* w = (n & 1) ? cvw : smw;
        float v = w[l * 12288 + (p * 64 + k) * 64 + (n >> 1)];
        __nv_bfloat16 h, lo;
        split_bf16(v, h, lo);
        g_wsn_h[idx] = h;
        g_wsn_l[idx] = lo;
    } else if (idx < LL * 3 * 8192 + 4096) {
        int j = idx - LL * 3 * 8192;
        int n = j >> 6, k = j & 63;
        float v = (k < ED_F) ? pew[k * 64 + n] : 0.f;
        __nv_bfloat16 h, lo;
        split_bf16(v, h, lo);
        g_wpe_h[j] = h;
        g_wpe_l[j] = lo;
    }
}

// ================= edge embed on tensor cores ================================
// 64 edges/block; M=64 N=64 K=64 (K rows 50..63 zero-padded in A and B).
__global__ __launch_bounds__(256) void edge_embed_tc_kernel(
    const float* __restrict__ A, const float* __restrict__ bias)
{
    extern __shared__ __nv_bfloat16 smbuf[];
    __nv_bfloat16* Ah = smbuf;
    __nv_bfloat16* Al = smbuf + 64 * TP;
    __nv_bfloat16* Bh = smbuf + 128 * TP;
    __nv_bfloat16* Bl = smbuf + 192 * TP;
    float* Sacc = (float*)smbuf;     /* pitch 80; 20480B fits (A+B dead) */
    __shared__ float biassm[64];

    const int tid = threadIdx.x;
    const int e0 = blockIdx.x * 64;

    if (tid < 64) biassm[tid] = bias[tid];

    for (int i = tid; i < 4608; i += 256) ((unsigned*)Ah)[i] = 0u;
    for (int i = tid; i < 1024; i += 256) {
        int p = i >> 9, n = (i >> 3) & 63, q = i & 7;
        uint4 v = *(const uint4*)&(p ? g_wpe_l : g_wpe_h)[n * 64 + q * 8];
        *(uint4*)&(p ? Bl : Bh)[n * TP + q * 8] = v;
    }
    __syncthreads();

    for (int i = tid; i < 64 * ED_F; i += 256) {
        float v = A[(size_t)e0 * ED_F + i];
        int r = i / ED_F, c = i - r * ED_F;
        __nv_bfloat16 h, lo;
        split_bf16(v, h, lo);
        Ah[r * TP + c] = h;
        Al[r * TP + c] = lo;
    }
    __syncthreads();

    const int lane = tid & 31, warp = tid >> 5;
    const int wm = warp >> 2, wn = warp & 3;
    const int g = lane >> 2, tg = lane & 3;

    float acc[2][2][4];
#pragma unroll
    for (int a = 0; a < 2; a++)
#pragma unroll
        for (int b = 0; b < 2; b++)
#pragma unroll
            for (int c = 0; c < 4; c++) acc[a][b][c] = 0.f;

#pragma unroll
    for (int ks = 0; ks < 4; ks++) {
        const int kb = ks * 16 + tg * 2;
        unsigned ah[2][4], alr[2][4], bh[2][2], blr[2][2];
#pragma unroll
        for (int mt = 0; mt < 2; mt++) {
            int r = wm * 32 + mt * 16 + g;
            ah[mt][0]  = *(const unsigned*)&Ah[r * TP + kb];
            ah[mt][1]  = *(const unsigned*)&Ah[(r + 8) * TP + kb];
            ah[mt][2]  = *(const unsigned*)&Ah[r * TP + kb + 8];
            ah[mt][3]  = *(const unsigned*)&Ah[(r + 8) * TP + kb + 8];
            alr[mt][0] = *(const unsigned*)&Al[r * TP + kb];
            alr[mt][1] = *(const unsigned*)&Al[(r + 8) * TP + kb];
            alr[mt][2] = *(const unsigned*)&Al[r * TP + kb + 8];
            alr[mt][3] = *(const unsigned*)&Al[(r + 8) * TP + kb + 8];
        }
#pragma unroll
        for (int nt = 0; nt < 2; nt++) {
            int n = wn * 16 + nt * 8 + g;
            bh[nt][0]  = *(const unsigned*)&Bh[n * TP + kb];
            bh[nt][1]  = *(const unsigned*)&Bh[n * TP + kb + 8];
            blr[nt][0] = *(const unsigned*)&Bl[n * TP + kb];
            blr[nt][1] = *(const unsigned*)&Bl[n * TP + kb + 8];
        }
#pragma unroll
        for (int mt = 0; mt < 2; mt++)
#pragma unroll
            for (int nt = 0; nt < 2; nt++) {
                mma_bf16(acc[mt][nt], ah[mt],  bh[nt]);
                mma_bf16(acc[mt][nt], ah[mt],  blr[nt]);
                mma_bf16(acc[mt][nt], alr[mt], bh[nt]);
            }
    }

    __syncthreads();
#pragma unroll
    for (int mt = 0; mt < 2; mt++)
#pragma unroll
        for (int nt = 0; nt < 2; nt++) {
            int r = wm * 32 + mt * 16 + g;
            int pc = wn * 16 + nt * 8 + 2 * tg;
            *(float2*)&Sacc[r * 80 + pc]       = make_float2(acc[mt][nt][0], acc[mt][nt][1]);
            *(float2*)&Sacc[(r + 8) * 80 + pc] = make_float2(acc[mt][nt][2], acc[mt][nt][3]);
        }
    __syncthreads();

    const int n_loc = tid >> 2, q4 = tid & 3;
    const int e = e0 + n_loc;
#pragma unroll
    for (int i = 0; i < 4; i++) {
        int c = i * 16 + q4 * 4;
        float4 sv = *(const float4*)&Sacc[n_loc * 80 + c];
        float v0 = fmaxf(sv.x + biassm[c + 0], 0.f);
        float v1 = fmaxf(sv.y + biassm[c + 1], 0.f);
        float v2 = fmaxf(sv.z + biassm[c + 2], 0.f);
        float v3 = fmaxf(sv.w + biassm[c + 3], 0.f);
        __nv_bfloat16 h0, l0, h1, l1, h2, l2, h3, l3;
        split_bf16(v0, h0, l0); split_bf16(v1, h1, l1);
        split_bf16(v2, h2, l2); split_bf16(v3, h3, l3);
        size_t base = (size_t)e * 64 + c;
        *(__nv_bfloat162*)&g_ea_h[base]     = __halves2bfloat162(h0, h1);
        *(__nv_bfloat162*)&g_ea_h[base + 2] = __halves2bfloat162(h2, h3);
        *(__nv_bfloat162*)&g_ea_l[base]     = __halves2bfloat162(l0, l1);
        *(__nv_bfloat162*)&g_ea_l[base + 2] = __halves2bfloat162(l2, l3);
    }
}

// ================= node projections (tensor cores, merged d+s) ===============
__global__ __launch_bounds__(256, 3) void node_proj_kernel(
    const float* __restrict__ smb, const float* __restrict__ cvb, int l)
{
    extern __shared__ __nv_bfloat16 smbuf[];
    __nv_bfloat16* Ah = smbuf;
    __nv_bfloat16* Al = Ah + 64 * TP;
    __nv_bfloat16* Bh = Al + 64 * TP;
    __nv_bfloat16* Bl = Bh + 128 * TP;
    float* Sacc = (float*)(smbuf + 2 * 64 * TP);
    __shared__ float biassm[128];

    const int tid = threadIdx.x;
    const int r0 = blockIdx.x * 64;

    if (tid < 128)
        biassm[tid] = ((tid & 1) ? cvb : smb)[l * 64 + (tid >> 1)];

    {
        const float4 z4 = make_float4(0.f, 0.f, 0.f, 0.f);
        for (int i = tid; i < 64 * 16; i += 256) {
            int gr = r0 + (i >> 4);
            if (gr < NN) *(float4*)&g_agg[(size_t)gr * 64 + (i & 15) * 4] = z4;
        }
        if (blockIdx.x == 0 && tid < 128) g_stats[tid] = 0.0;
    }

    for (int i = tid; i < 1024; i += 256) {
        int p = i >> 9, r = (i >> 3) & 63, q = i & 7;
        int gr = r0 + r;
        uint4 v = make_uint4(0u, 0u, 0u, 0u);
        if (gr < NN)
            v = *(const uint4*)&(p ? g_x_l : g_x_h)[(size_t)gr * 64 + q * 8];
        *(uint4*)&(p ? Al : Ah)[r * TP + q * 8] = v;
    }

    const int lane = tid & 31, warp = tid >> 5;
    const int wm = warp >> 2, wn = warp & 3;
    const int g = lane >> 2, tg = lane & 3;

#pragma unroll
    for (int y = 0; y < 2; y++) {
        __syncthreads();
        const int wofs = (l * 3 + y) * 8192;
        for (int i = tid; i < 2048; i += 256) {
            int p = i >> 10, n = (i >> 3) & 127, q = i & 7;
            uint4 v = *(const uint4*)&(p ? g_wsn_l : g_wsn_h)[wofs + n * 64 + q * 8];
            *(uint4*)&(p ? Bl : Bh)[n * TP + q * 8] = v;
        }
        __syncthreads();

        float acc[2][4][4];
#pragma unroll
        for (int a = 0; a < 2; a++)
#pragma unroll
            for (int b = 0; b < 4; b++)
#pragma unroll
                for (int c = 0; c < 4; c++) acc[a][b][c] = 0.f;

#pragma unroll
        for (int ks = 0; ks < 4; ks++) {
            const int kb = ks * 16 + tg * 2;
            unsigned ah[2][4], alr[2][4], bh[4][2], blr[4][2];
#pragma unroll
            for (int mt = 0; mt < 2; mt++) {
                int r = wm * 32 + mt * 16 + g;
                ah[mt][0]  = *(const unsigned*)&Ah[r * TP + kb];
                ah[mt][1]  = *(const unsigned*)&Ah[(r + 8) * TP + kb];
                ah[mt][2]  = *(const unsigned*)&Ah[r * TP + kb + 8];
                ah[mt][3]  = *(const unsigned*)&Ah[(r + 8) * TP + kb + 8];
                alr[mt][0] = *(const unsigned*)&Al[r * TP + kb];
                alr[mt][1] = *(const unsigned*)&Al[(r + 8) * TP + kb];
                alr[mt][2] = *(const unsigned*)&Al[r * TP + kb + 8];
                alr[mt][3] = *(const unsigned*)&Al[(r + 8) * TP + kb + 8];
            }
#pragma unroll
            for (int nt = 0; nt < 4; nt++) {
                int n = wn * 32 + nt * 8 + g;
                bh[nt][0]  = *(const unsigned*)&Bh[n * TP + kb];
                bh[nt][1]  = *(const unsigned*)&Bh[n * TP + kb + 8];
                blr[nt][0] = *(const unsigned*)&Bl[n * TP + kb];
                blr[nt][1] = *(const unsigned*)&Bl[n * TP + kb + 8];
            }
#pragma unroll
            for (int mt = 0; mt < 2; mt++)
#pragma unroll
                for (int nt = 0; nt < 4; nt++) {
                    mma_bf16(acc[mt][nt], ah[mt],  bh[nt]);
                    mma_bf16(acc[mt][nt], ah[mt],  blr[nt]);
                    mma_bf16(acc[mt][nt], alr[mt], bh[nt]);
                }
        }

        __syncthreads();
#pragma unroll
        for (int mt = 0; mt < 2; mt++)
#pragma unroll
            for (int nt = 0; nt < 4; nt++) {
                int r = wm * 32 + mt * 16 + g;
                int pc = wn * 32 + nt * 8 + 2 * tg;
                *(float2*)&Sacc[r * 132 + pc]       = make_float2(acc[mt][nt][0], acc[mt][nt][1]);
                *(float2*)&Sacc[(r + 8) * 132 + pc] = make_float2(acc[mt][nt][2], acc[mt][nt][3]);
            }
        __syncthreads();

        const int n_loc = tid >> 2, q4 = tid & 3;
        const int n = r0 + n_loc;
        if (n < NN) {
            float* dsta = (y == 0 ? g_xprojd : g_xprojs) + (size_t)n * 128;
#pragma unroll
            for (int i = 0; i < 8; i++) {
                int c = i * 16 + q4 * 4;
                float4 sv = *(const float4*)&Sacc[n_loc * 132 + c];
                float4 v;
                if (y == 0) {
                    v.x = sv.x + biassm[c + 0];
                    v.y = sv.y + biassm[c + 1];
                    v.z = sv.z + biassm[c + 2];
                    v.w = sv.w + biassm[c + 3];
                } else {
                    v = sv;
                }
                *(float4*)&dsta[c] = v;
            }
        }
    }
}

// ================= fused edge GEMM + staged epilogue =========================
__global__ __launch_bounds__(256, 3) void edge_conv_kernel(
    const int* __restrict__ eidx, int l)
{
    extern __shared__ __nv_bfloat16 smbuf[];
    __nv_bfloat16* Ah = smbuf;
    __nv_bfloat16* Al = Ah + 64 * TP;
    __nv_bfloat16* Bh = Al + 64 * TP;
    __nv_bfloat16* Bl = Bh + 128 * TP;

    const int tid = threadIdx.x;
    const int e0 = blockIdx.x * 64;

    const int e_loc = tid >> 2, q4 = tid & 3;
    const int e = e0 + e_loc;
    const int s = eidx[e], d = eidx[EE + e];

    for (int i = tid; i < 1024; i += 256) {
        int p = i >> 9, r = (i >> 3) & 63, q = i & 7;
        uint4 v = *(const uint4*)&(p ? g_ea_l : g_ea_h)[(size_t)(e0 + r) * 64 + q * 8];
        *(uint4*)&(p ? Al : Ah)[r * TP + q * 8] = v;
    }
    const int wofs = (l * 3 + 2) * 8192;
    for (int i = tid; i < 2048; i += 256) {
        int p = i >> 10, n = (i >> 3) & 127, q = i & 7;
        uint4 v = *(const uint4*)&(p ? g_wsn_l : g_wsn_h)[wofs + n * 64 + q * 8];
        *(uint4*)&(p ? Bl : Bh)[n * TP + q * 8] = v;
    }
    __syncthreads();

    const int lane = tid & 31, warp = tid >> 5;
    const int wm = warp >> 2, wn = warp & 3;
    const int g = lane >> 2, tg = lane & 3;

    float acc[2][4][4];
#pragma unroll
    for (int a = 0; a < 2; a++)
#pragma unroll
        for (int b = 0; b < 4; b++)
#pragma unroll
            for (int c = 0; c < 4; c++) acc[a][b][c] = 0.f;

#pragma unroll
    for (int ks = 0; ks < 4; ks++) {
        const int kb = ks * 16 + tg * 2;
        unsigned ah[2][4], alr[2][4], bh[4][2], blr[4][2];
#pragma unroll
        for (int mt = 0; mt < 2; mt++) {
            int r = wm * 32 + mt * 16 + g;
            ah[mt][0]  = *(const unsigned*)&Ah[r * TP + kb];
            ah[mt][1]  = *(const unsigned*)&Ah[(r + 8) * TP + kb];
            ah[mt][2]  = *(const unsigned*)&Ah[r * TP + kb + 8];
            ah[mt][3]  = *(const unsigned*)&Ah[(r + 8) * TP + kb + 8];
            alr[mt][0] = *(const unsigned*)&Al[r * TP + kb];
            alr[mt][1] = *(const unsigned*)&Al[(r + 8) * TP + kb];
            alr[mt][2] = *(const unsigned*)&Al[r * TP + kb + 8];
            alr[mt][3] = *(const unsigned*)&Al[(r + 8) * TP + kb + 8];
        }
#pragma unroll
        for (int nt = 0; nt < 4; nt++) {
            int n = wn * 32 + nt * 8 + g;
            bh[nt][0]  = *(const unsigned*)&Bh[n * TP + kb];
            bh[nt][1]  = *(const unsigned*)&Bh[n * TP + kb + 8];
            blr[nt][0] = *(const unsigned*)&Bl[n * TP + kb];
            blr[nt][1] = *(const unsigned*)&Bl[n * TP + kb + 8];
        }
#pragma unroll
        for (int mt = 0; mt < 2; mt++)
#pragma unroll
            for (int nt = 0; nt < 4; nt++) {
                mma_bf16(acc[mt][nt], ah[mt],  bh[nt]);
                mma_bf16(acc[mt][nt], ah[mt],  blr[nt]);
                mma_bf16(acc[mt][nt], alr[mt], bh[nt]);
            }
    }

    __syncthreads();
    float* Sacc = (float*)smbuf;
#pragma unroll
    for (int mt = 0; mt < 2; mt++)
#pragma unroll
        for (int nt = 0; nt < 4; nt++) {
            int r = wm * 32 + mt * 16 + g;
            int pc = wn * 32 + nt * 8 + 2 * tg;
            *(float2*)&Sacc[r * 132 + pc]       = make_float2(acc[mt][nt][0], acc[mt][nt][1]);
            *(float2*)&Sacc[(r + 8) * 132 + pc] = make_float2(acc[mt][nt][2], acc[mt][nt][3]);
        }
    __syncthreads();

    const float* pdp = &g_xprojd[(size_t)d * 128];
    const float* psp = &g_xprojs[(size_t)s * 128];
#pragma unroll
    for (int i = 0; i < 4; i++) {
        int c = i * 32 + q4 * 8;
        float4 pd0 = *(const float4*)&pdp[c];
        float4 pd1 = *(const float4*)&pdp[c + 4];
        float4 ps0 = *(const float4*)&psp[c];
        float4 ps1 = *(const float4*)&psp[c + 4];
        float4 sa0 = *(const float4*)&Sacc[e_loc * 132 + c];
        float4 sa1 = *(const float4*)&Sacc[e_loc * 132 + c + 4];
        float4 o;
        o.x = msg_f(sa0.x + pd0.x + ps0.x, sa0.y + pd0.y + ps0.y);
        o.y = msg_f(sa0.z + pd0.z + ps0.z, sa0.w + pd0.w + ps0.w);
        o.z = msg_f(sa1.x + pd1.x + ps1.x, sa1.y + pd1.y + ps1.y);
        o.w = msg_f(sa1.z + pd1.z + ps1.z, sa1.w + pd1.w + ps1.w);
        atomicAdd((float4*)&g_agg[(size_t)d * 64 + i * 16 + q4 * 4], o);
    }
}

// ================= BN statistics =============================================
__global__ __launch_bounds__(256) void bn_stats_kernel()
{
    const int tid = threadIdx.x;
    const int c = tid & 63;
    const int rl = tid >> 6;
    float s = 0.f, s2 = 0.f;
    for (int r = blockIdx.x * 4 + rl; r < NN; r += gridDim.x * 4) {
        float v = g_agg[r * 64 + c];
        s += v; s2 += v * v;
    }
    __shared__ float sh[512];
    sh[tid] = s; sh[256 + tid] = s2;
    __syncthreads();
    if (tid < 64) {
        float ts = sh[tid] + sh[tid + 64] + sh[tid + 128] + sh[tid + 192];
        float t2 = sh[256 + tid] + sh[256 + tid + 64] + sh[256 + tid + 128] + sh[256 + tid + 192];
        atomicAdd(&g_stats[tid], (double)ts);
        atomicAdd(&g_stats[64 + tid], (double)t2);
    }
}

// ================= BN apply + residual (+ bf16 planes) =======================
__global__ __launch_bounds__(256) void bn_apply_kernel(
    const float* __restrict__ gamma, const float* __restrict__ beta, int l)
{
    __shared__ float sc[64], sf[64];
    const int tid = threadIdx.x;
    if (tid < 64) {
        double mu = g_stats[tid] * (1.0 / NN);
        double var = g_stats[64 + tid] * (1.0 / NN) - mu * mu;
        float rstd = rsqrtf((float)var + BN_EPS);
        float s = rstd * gamma[l * 64 + tid];
        sc[tid] = s;
        sf[tid] = beta[l * 64 + tid] - (float)mu * s;
    }
    __syncthreads();

    int idx = blockIdx.x * 256 + tid;
    if (idx >= NN * 16) return;
    int r = idx >> 4, c = (idx & 15) * 4;
    size_t base = (size_t)r * 64 + c;
    float4 a = *(const float4*)&g_agg[base];
    float4 x = *(const float4*)&g_x[base];
    float4 nx;
    nx.x = x.x + a.x * sc[c + 0] + sf[c + 0];
    nx.y = x.y + a.y * sc[c + 1] + sf[c + 1];
    nx.z = x.z + a.z * sc[c + 2] + sf[c + 2];
    nx.w = x.w + a.w * sc[c + 3] + sf[c + 3];
    *(float4*)&g_x[base] = nx;
    __nv_bfloat16 h0, l0, h1, l1, h2, l2, h3, l3;
    split_bf16(nx.x, h0, l0); split_bf16(nx.y, h1, l1);
    split_bf16(nx.z, h2, l2); split_bf16(nx.w, h3, l3);
    *(__nv_bfloat162*)&g_x_h[base]     = __halves2bfloat162(h0, h1);
    *(__nv_bfloat162*)&g_x_h[base + 2] = __halves2bfloat162(h2, h3);
    *(__nv_bfloat162*)&g_x_l[base]     = __halves2bfloat162(l0, l1);
    *(__nv_bfloat162*)&g_x_l[base + 2] = __halves2bfloat162(l2, l3);
}

// ================= zero / pool / head ========================================
__global__ void zero_pool_kernel()
{
    int idx = blockIdx.x * 256 + threadIdx.x;
    if (idx < GG * 64) g_pool[idx] = 0.f;
    if (idx < GG) g_cnt[idx] = 0.f;
}

__global__ __launch_bounds__(256) void pool_kernel(const int* __restrict__ batch)
{
    int idx = blockIdx.x * 256 + threadIdx.x;
    if (idx >= NN * 16) return;
    int r = idx >> 4, cs = (idx & 15) * 4;
    float4 v = *(const float4*)&g_y[(size_t)r * 64 + cs];
    int g = batch[r];
    atomicAdd((float4*)&g_pool[g * 64 + cs], v);
    if ((idx & 15) == 0) atomicAdd(&g_cnt[g], 1.f);
}

__global__ __launch_bounds__(64) void head_kernel(
    const float* __restrict__ hw, const float* __restrict__ hb,
    const float* __restrict__ ow, const float* __restrict__ ob,
    float* __restrict__ out)
{
    __shared__ float v[64];
    __shared__ float red[64];
    const int g = blockIdx.x, c = threadIdx.x;
    v[c] = g_pool[g * 64 + c] / fmaxf(g_cnt[g], 1.f);
    __syncthreads();
#pragma unroll
    for (int j = 0; j < 2; j++) {
        float acc = hb[j * 64 + c];
        const float* W = hw + j * 4096;
#pragma unroll 8
        for (int k = 0; k < 64; k++) acc += v[k] * W[k * 64 + c];
        __syncthreads();
        v[c] = fmaxf(acc, 0.f);
        __syncthreads();
    }
    red[c] = v[c] * ow[c];
    __syncthreads();
    if (c < 32) {
        float t = red[c] + red[c + 32];
#pragma unroll
        for (int off = 16; off > 0; off >>= 1)
            t += __shfl_down_sync(0xffffffffu, t, off);
        if (c == 0) out[g] = t + ob[0];
    }
}

// ================= launch ====================================================
extern "C" void kernel_launch(void* const* d_in, const int* in_sizes, int n_in,
                              void* d_out, int out_size)
{
    const float* x_in  = (const float*)d_in[0];
    const int*   eidx  = (const int*)  d_in[1];
    const float* eattr = (const float*)d_in[2];
    const int*   batch = (const int*)  d_in[3];
    const float* pnw = (const float*)d_in[4];
    const float* pnb = (const float*)d_in[5];
    const float* pew = (const float*)d_in[6];
    const float* peb = (const float*)d_in[7];
    const float* smw = (const float*)d_in[8];
    const float* smb = (const float*)d_in[9];
    const float* cvw = (const float*)d_in[10];
    const float* cvb = (const float*)d_in[11];
    const float* gam = (const float*)d_in[12];
    const float* bet = (const float*)d_in[13];
    const float* ppw = (const float*)d_in[14];
    const float* ppb = (const float*)d_in[15];
    const float* hw  = (const float*)d_in[16];
    const float* hb  = (const float*)d_in[17];
    const float* ow  = (const float*)d_in[18];
    const float* ob  = (const float*)d_in[19];
    float* out = (float*)d_out;

    float* p_x; cudaGetSymbolAddress((void**)&p_x, g_x);
    float* p_y; cudaGetSymbolAddress((void**)&p_y, g_y);

    const int NODE_BLOCKS = (NN + 63) / 64;
    const int EDGE_BLOCKS = EE / 64;
    const int VEC_BLOCKS  = (NN * 16 + 255) / 256;
    const int MMA_SMEM = (2 * 64 * TP + 2 * 128 * TP) * 2;
    const int EM_SMEM  = 4 * 64 * TP * 2;

    cudaFuncSetAttribute(edge_conv_kernel,
                         cudaFuncAttributeMaxDynamicSharedMemorySize, MMA_SMEM);
    cudaFuncSetAttribute(node_proj_kernel,
                         cudaFuncAttributeMaxDynamicSharedMemorySize, MMA_SMEM);
    cudaFuncSetAttribute(edge_embed_tc_kernel,
                         cudaFuncAttributeMaxDynamicSharedMemorySize, EM_SMEM);

    prep_wsplit_kernel<<<(LL * 3 * 8192 + 4096 + 255) / 256, 256>>>(smw, cvw, pew);
    embed_kernel<IN_F, IN_F + 1, true><<<NODE_BLOCKS, 256>>>(x_in, pnw, pnb, p_x, NN);
    edge_embed_tc_kernel<<<EDGE_BLOCKS, 256, EM_SMEM>>>(eattr, peb);

    for (int l = 0; l < LL; l++) {
        node_proj_kernel<<<NODE_BLOCKS, 256, MMA_SMEM>>>(smb, cvb, l);
        edge_conv_kernel<<<EDGE_BLOCKS, 256, MMA_SMEM>>>(eidx, l);
        bn_stats_kernel<<<128, 256>>>();
        bn_apply_kernel<<<VEC_BLOCKS, 256>>>(gam, bet, l);
    }

    embed_kernel<HH, HH + 1, false><<<NODE_BLOCKS, 256>>>(p_x, ppw, ppb, p_y, NN);
    zero_pool_kernel<<<(GG * 64 + 255) / 256, 256>>>();
    pool_kernel<<<VEC_BLOCKS, 256>>>(batch);
    head_kernel<<<GG, 64>>>(hw, hb, ow, ob, out);
}

// round 16
// speedup vs baseline: 1.0329x; 1.0329x over previous
#include <cuda_runtime.h>
#include <cuda_bf16.h>
#include <math.h>

// Problem constants (fixed by the dataset)
#define NN 50000
#define EE 800000
#define IN_F 92
#define ED_F 50
#define HH 64
#define LL 4
#define GG 512
#define BN_EPS 1e-5f
#define TP 72   // bf16 tile pitch: 144B rows -> conflict-free fragment LDS/ldmatrix

// ---------------- scratch (device globals; no allocations allowed) ----------
__device__ float          g_x[NN * HH];       // node features fp32 (current layer)
__device__ __nv_bfloat16  g_x_h[NN * HH];     // node features hi plane
__device__ __nv_bfloat16  g_x_l[NN * HH];     // node features lo plane
__device__ __nv_bfloat16  g_ea_h[EE * HH];    // edge embed hi plane
__device__ __nv_bfloat16  g_ea_l[EE * HH];    // edge embed lo plane
__device__ __nv_bfloat16  g_wsn_h[LL * 3 * 8192]; // weight planes [l][p][n(128)][k(64)]
__device__ __nv_bfloat16  g_wsn_l[LL * 3 * 8192];
__device__ float          g_xprojd[NN * 128]; // dst proj (incl. bias)
__device__ float          g_xprojs[NN * 128]; // src proj (no bias)
__device__ float          g_agg[NN * HH];     // per-layer aggregated messages
__device__ double         g_stats[128];       // BN sums
__device__ float          g_y[NN * HH];       // pre-pool features
__device__ float          g_pool[GG * HH];    // pooled sums
__device__ float          g_cnt[GG];          // per-graph node counts

// ---------------- helpers ----------------------------------------------------
__device__ __forceinline__ float softplus_f(float x) {
    return fmaxf(x, 0.f) + __logf(1.f + __expf(-fabsf(x)));
}
__device__ __forceinline__ float sigmoid_f(float x) {
    return __fdividef(1.f, 1.f + __expf(-x));
}
__device__ __forceinline__ float msg_f(float S, float C) {
    return softplus_f(S) * sigmoid_f(C);
}
__device__ __forceinline__ void split_bf16(float v, __nv_bfloat16& h, __nv_bfloat16& l) {
    h = __float2bfloat16(v);
    l = __float2bfloat16(v - __bfloat162float(h));
}
__device__ __forceinline__ void mma_bf16(float c[4], const unsigned a[4], const unsigned b[2]) {
    asm volatile(
        "mma.sync.aligned.m16n8k16.row.col.f32.bf16.bf16.f32 "
        "{%0,%1,%2,%3}, {%4,%5,%6,%7}, {%8,%9}, {%0,%1,%2,%3};"
        : "+f"(c[0]), "+f"(c[1]), "+f"(c[2]), "+f"(c[3])
        : "r"(a[0]), "r"(a[1]), "r"(a[2]), "r"(a[3]), "r"(b[0]), "r"(b[1]));
}
__device__ __forceinline__ void ldm_x4(unsigned r[4], unsigned saddr) {
    asm volatile("ldmatrix.sync.aligned.m8n8.x4.shared.b16 {%0,%1,%2,%3}, [%4];"
                 : "=r"(r[0]), "=r"(r[1]), "=r"(r[2]), "=r"(r[3]) : "r"(saddr));
}

// ---------------- generic [rows,K]@[K,64] + bias + relu (fp32 out) -----------
template <int K, int KP, bool EMIT>
__global__ __launch_bounds__(256) void embed_kernel(
    const float* __restrict__ A, const float* __restrict__ W,
    const float* __restrict__ bias, float* __restrict__ out, int nrows)
{
    __shared__ float As[64 * KP];
    __shared__ float Bs[K * 64];
    const int r0 = blockIdx.x * 64;
    const int tid = threadIdx.x;

    for (int i = tid; i < 64 * K; i += 256) {
        int r = i / K, k = i - r * K;
        int gr = r0 + r;
        As[r * KP + k] = (gr < nrows) ? A[(size_t)gr * K + k] : 0.f;
    }
    for (int i = tid; i < K * 64; i += 256) Bs[i] = W[i];
    __syncthreads();

    const int rx = tid >> 4, cx = tid & 15;
    float acc[4][4];
#pragma unroll
    for (int i = 0; i < 4; i++)
#pragma unroll
        for (int j = 0; j < 4; j++) acc[i][j] = 0.f;

#pragma unroll 4
    for (int k = 0; k < K; k++) {
        float4 b = *(const float4*)&Bs[k * 64 + cx * 4];
#pragma unroll
        for (int i = 0; i < 4; i++) {
            float a = As[(rx * 4 + i) * KP + k];
            acc[i][0] += a * b.x; acc[i][1] += a * b.y;
            acc[i][2] += a * b.z; acc[i][3] += a * b.w;
        }
    }
    float4 bb = *(const float4*)&bias[cx * 4];
#pragma unroll
    for (int i = 0; i < 4; i++) {
        int gr = r0 + rx * 4 + i;
        if (gr < nrows) {
            float4 v;
            v.x = fmaxf(acc[i][0] + bb.x, 0.f);
            v.y = fmaxf(acc[i][1] + bb.y, 0.f);
            v.z = fmaxf(acc[i][2] + bb.z, 0.f);
            v.w = fmaxf(acc[i][3] + bb.w, 0.f);
            size_t base = (size_t)gr * 64 + cx * 4;
            *(float4*)&out[base] = v;
            if (EMIT) {
                __nv_bfloat16 h0, l0, h1, l1, h2, l2, h3, l3;
                split_bf16(v.x, h0, l0); split_bf16(v.y, h1, l1);
                split_bf16(v.z, h2, l2); split_bf16(v.w, h3, l3);
                *(__nv_bfloat162*)&g_x_h[base]     = __halves2bfloat162(h0, h1);
                *(__nv_bfloat162*)&g_x_h[base + 2] = __halves2bfloat162(h2, h3);
                *(__nv_bfloat162*)&g_x_l[base]     = __halves2bfloat162(l0, l1);
                *(__nv_bfloat162*)&g_x_l[base + 2] = __halves2bfloat162(l2, l3);
            }
        }
    }
}

// ---------------- edge embed: [E,50]@[50,64]+bias+relu -> bf16 hi/lo planes --
__global__ __launch_bounds__(256) void embed_edge_kernel(
    const float* __restrict__ A, const float* __restrict__ W,
    const float* __restrict__ bias)
{
    const int K = ED_F, KP = ED_F + 1;
    __shared__ float As[64 * (ED_F + 1)];
    __shared__ float Bs[ED_F * 64];
    const int r0 = blockIdx.x * 64;
    const int tid = threadIdx.x;

    for (int i = tid; i < 64 * K; i += 256) {
        int r = i / K, k = i - r * K;
        As[r * KP + k] = A[(size_t)(r0 + r) * K + k];   // EE % 64 == 0
    }
    for (int i = tid; i < K * 64; i += 256) Bs[i] = W[i];
    __syncthreads();

    const int rx = tid >> 4, cx = tid & 15;
    float acc[4][4];
#pragma unroll
    for (int i = 0; i < 4; i++)
#pragma unroll
        for (int j = 0; j < 4; j++) acc[i][j] = 0.f;

#pragma unroll 2
    for (int k = 0; k < K; k++) {
        float4 b = *(const float4*)&Bs[k * 64 + cx * 4];
#pragma unroll
        for (int i = 0; i < 4; i++) {
            float a = As[(rx * 4 + i) * KP + k];
            acc[i][0] += a * b.x; acc[i][1] += a * b.y;
            acc[i][2] += a * b.z; acc[i][3] += a * b.w;
        }
    }
    float4 bb = *(const float4*)&bias[cx * 4];
#pragma unroll
    for (int i = 0; i < 4; i++) {
        int gr = r0 + rx * 4 + i;
        float v0 = fmaxf(acc[i][0] + bb.x, 0.f);
        float v1 = fmaxf(acc[i][1] + bb.y, 0.f);
        float v2 = fmaxf(acc[i][2] + bb.z, 0.f);
        float v3 = fmaxf(acc[i][3] + bb.w, 0.f);
        __nv_bfloat16 h0, l0, h1, l1, h2, l2, h3, l3;
        split_bf16(v0, h0, l0); split_bf16(v1, h1, l1);
        split_bf16(v2, h2, l2); split_bf16(v3, h3, l3);
        size_t base = (size_t)gr * 64 + cx * 4;
        *(__nv_bfloat162*)&g_ea_h[base]     = __halves2bfloat162(h0, h1);
        *(__nv_bfloat162*)&g_ea_h[base + 2] = __halves2bfloat162(h2, h3);
        *(__nv_bfloat162*)&g_ea_l[base]     = __halves2bfloat162(l0, l1);
        *(__nv_bfloat162*)&g_ea_l[base + 2] = __halves2bfloat162(l2, l3);
    }
}

// ---------------- weight split planes (all layers / parts, once) -------------
__global__ void prep_wsplit_kernel(const float* __restrict__ smw,
                                   const float* __restrict__ cvw)
{
    int idx = blockIdx.x * 256 + threadIdx.x;
    if (idx >= LL * 3 * 8192) return;
    int l = idx / (3 * 8192);
    int rem = idx - l * 3 * 8192;
    int p = rem >> 13;
    int r = rem & 8191;
    int n = r >> 6, k = r & 63;
    const float* w = (n & 1) ? cvw : smw;
    float v = w[l * 12288 + (p * 64 + k) * 64 + (n >> 1)];
    __nv_bfloat16 h, lo;
    split_bf16(v, h, lo);
    g_wsn_h[idx] = h;
    g_wsn_l[idx] = lo;
}

// ---------------- node projections via tensor cores (merged d+s phases) ------
__global__ __launch_bounds__(256, 3) void node_proj_kernel(
    const float* __restrict__ smb, const float* __restrict__ cvb, int l)
{
    extern __shared__ __nv_bfloat16 smbuf[];
    __nv_bfloat16* Ah = smbuf;                       // [64][TP]
    __nv_bfloat16* Al = Ah + 64 * TP;
    __nv_bfloat16* Bh = Al + 64 * TP;                // [128][TP]
    __nv_bfloat16* Bl = Bh + 128 * TP;
    float* Sacc = (float*)(smbuf + 2 * 64 * TP);     // overlays B region
    __shared__ float biassm[128];

    const int tid = threadIdx.x;
    const int r0 = blockIdx.x * 64;

    if (tid < 128)
        biassm[tid] = ((tid & 1) ? cvb : smb)[l * 64 + (tid >> 1)];

    // fold in the agg/stats zeroing
    {
        const float4 z4 = make_float4(0.f, 0.f, 0.f, 0.f);
        for (int i = tid; i < 64 * 16; i += 256) {
            int gr = r0 + (i >> 4);
            if (gr < NN) *(float4*)&g_agg[(size_t)gr * 64 + (i & 15) * 4] = z4;
        }
        if (blockIdx.x == 0 && tid < 128) g_stats[tid] = 0.0;
    }

    // load A once, uint4-vectorized (stays resident across both phases)
    for (int i = tid; i < 1024; i += 256) {
        int p = i >> 9, r = (i >> 3) & 63, q = i & 7;
        int gr = r0 + r;
        uint4 v = make_uint4(0u, 0u, 0u, 0u);
        if (gr < NN)
            v = *(const uint4*)&(p ? g_x_l : g_x_h)[(size_t)gr * 64 + q * 8];
        *(uint4*)&(p ? Al : Ah)[r * TP + q * 8] = v;
    }

    const int lane = tid & 31, warp = tid >> 5;
    const int wm = warp >> 2, wn = warp & 3;
    const int g = lane >> 2, tg = lane & 3;
    const int quad = lane >> 3, li = lane & 7;

    // ldmatrix per-lane byte offsets
    unsigned a_off[2], b_off[2];
#pragma unroll
    for (int mt = 0; mt < 2; mt++)
        a_off[mt] = (unsigned)(((wm * 32 + mt * 16 + (quad & 1) * 8 + li) * TP
                               + (quad >> 1) * 8) * 2);
#pragma unroll
    for (int np = 0; np < 2; np++)
        b_off[np] = (unsigned)(((wn * 32 + np * 16 + (quad >> 1) * 8 + li) * TP
                               + (quad & 1) * 8) * 2);
    const unsigned sAh = (unsigned)__cvta_generic_to_shared(Ah);
    const unsigned sAl = (unsigned)__cvta_generic_to_shared(Al);
    const unsigned sBh = (unsigned)__cvta_generic_to_shared(Bh);
    const unsigned sBl = (unsigned)__cvta_generic_to_shared(Bl);

#pragma unroll
    for (int y = 0; y < 2; y++) {
        __syncthreads();
        const int wofs = (l * 3 + y) * 8192;
        for (int i = tid; i < 2048; i += 256) {
            int p = i >> 10, n = (i >> 3) & 127, q = i & 7;
            uint4 v = *(const uint4*)&(p ? g_wsn_l : g_wsn_h)[wofs + n * 64 + q * 8];
            *(uint4*)&(p ? Bl : Bh)[n * TP + q * 8] = v;
        }
        __syncthreads();

        float acc[2][4][4];
#pragma unroll
        for (int a = 0; a < 2; a++)
#pragma unroll
            for (int b = 0; b < 4; b++)
#pragma unroll
                for (int c = 0; c < 4; c++) acc[a][b][c] = 0.f;

#pragma unroll
        for (int ks = 0; ks < 4; ks++) {
            const unsigned kbyte = (unsigned)(ks * 32);
            unsigned ah[2][4], alr[2][4], bhp[2][4], blp[2][4];
#pragma unroll
            for (int mt = 0; mt < 2; mt++) {
                ldm_x4(ah[mt],  sAh + a_off[mt] + kbyte);
                ldm_x4(alr[mt], sAl + a_off[mt] + kbyte);
            }
#pragma unroll
            for (int np = 0; np < 2; np++) {
                ldm_x4(bhp[np], sBh + b_off[np] + kbyte);
                ldm_x4(blp[np], sBl + b_off[np] + kbyte);
            }
#pragma unroll
            for (int mt = 0; mt < 2; mt++)
#pragma unroll
                for (int nt = 0; nt < 4; nt++) {
                    const int np = nt >> 1, ix = (nt & 1) * 2;
                    mma_bf16(acc[mt][nt], ah[mt],  &bhp[np][ix]);
                    mma_bf16(acc[mt][nt], ah[mt],  &blp[np][ix]);
                    mma_bf16(acc[mt][nt], alr[mt], &bhp[np][ix]);
                }
        }

        __syncthreads();
#pragma unroll
        for (int mt = 0; mt < 2; mt++)
#pragma unroll
            for (int nt = 0; nt < 4; nt++) {
                int r = wm * 32 + mt * 16 + g;
                int pc = wn * 32 + nt * 8 + 2 * tg;
                *(float2*)&Sacc[r * 132 + pc]       = make_float2(acc[mt][nt][0], acc[mt][nt][1]);
                *(float2*)&Sacc[(r + 8) * 132 + pc] = make_float2(acc[mt][nt][2], acc[mt][nt][3]);
            }
        __syncthreads();

        const int n_loc = tid >> 2, q4 = tid & 3;
        const int n = r0 + n_loc;
        if (n < NN) {
            float* dsta = (y == 0 ? g_xprojd : g_xprojs) + (size_t)n * 128;
#pragma unroll
            for (int i = 0; i < 8; i++) {
                int c = i * 16 + q4 * 4;
                float4 sv = *(const float4*)&Sacc[n_loc * 132 + c];
                float4 v;
                if (y == 0) {
                    v.x = sv.x + biassm[c + 0];
                    v.y = sv.y + biassm[c + 1];
                    v.z = sv.z + biassm[c + 2];
                    v.w = sv.w + biassm[c + 3];
                } else {
                    v = sv;
                }
                *(float4*)&dsta[c] = v;
            }
        }
    }
}

// ---------------- fused edge GEMM (1-tile) + staged epilogue -----------------
__global__ __launch_bounds__(256, 3) void edge_conv_kernel(
    const int* __restrict__ eidx, int l)
{
    extern __shared__ __nv_bfloat16 smbuf[];
    __nv_bfloat16* Ah = smbuf;
    __nv_bfloat16* Al = Ah + 64 * TP;
    __nv_bfloat16* Bh = Al + 64 * TP;
    __nv_bfloat16* Bl = Bh + 128 * TP;

    const int tid = threadIdx.x;
    const int e0 = blockIdx.x * 64;            // EE % 64 == 0

    const int e_loc = tid >> 2, q4 = tid & 3;
    const int e = e0 + e_loc;
    const int s = eidx[e], d = eidx[EE + e];

    for (int i = tid; i < 1024; i += 256) {
        int p = i >> 9, r = (i >> 3) & 63, q = i & 7;
        uint4 v = *(const uint4*)&(p ? g_ea_l : g_ea_h)[(size_t)(e0 + r) * 64 + q * 8];
        *(uint4*)&(p ? Al : Ah)[r * TP + q * 8] = v;
    }
    const int wofs = (l * 3 + 2) * 8192;
    for (int i = tid; i < 2048; i += 256) {
        int p = i >> 10, n = (i >> 3) & 127, q = i & 7;
        uint4 v = *(const uint4*)&(p ? g_wsn_l : g_wsn_h)[wofs + n * 64 + q * 8];
        *(uint4*)&(p ? Bl : Bh)[n * TP + q * 8] = v;
    }
    __syncthreads();

    const int lane = tid & 31, warp = tid >> 5;
    const int wm = warp >> 2, wn = warp & 3;
    const int g = lane >> 2, tg = lane & 3;
    const int quad = lane >> 3, li = lane & 7;

    unsigned a_off[2], b_off[2];
#pragma unroll
    for (int mt = 0; mt < 2; mt++)
        a_off[mt] = (unsigned)(((wm * 32 + mt * 16 + (quad & 1) * 8 + li) * TP
                               + (quad >> 1) * 8) * 2);
#pragma unroll
    for (int np = 0; np < 2; np++)
        b_off[np] = (unsigned)(((wn * 32 + np * 16 + (quad >> 1) * 8 + li) * TP
                               + (quad & 1) * 8) * 2);
    const unsigned sAh = (unsigned)__cvta_generic_to_shared(Ah);
    const unsigned sAl = (unsigned)__cvta_generic_to_shared(Al);
    const unsigned sBh = (unsigned)__cvta_generic_to_shared(Bh);
    const unsigned sBl = (unsigned)__cvta_generic_to_shared(Bl);

    float acc[2][4][4];
#pragma unroll
    for (int a = 0; a < 2; a++)
#pragma unroll
        for (int b = 0; b < 4; b++)
#pragma unroll
            for (int c = 0; c < 4; c++) acc[a][b][c] = 0.f;

#pragma unroll
    for (int ks = 0; ks < 4; ks++) {
        const unsigned kbyte = (unsigned)(ks * 32);
        unsigned ah[2][4], alr[2][4], bhp[2][4], blp[2][4];
#pragma unroll
        for (int mt = 0; mt < 2; mt++) {
            ldm_x4(ah[mt],  sAh + a_off[mt] + kbyte);
            ldm_x4(alr[mt], sAl + a_off[mt] + kbyte);
        }
#pragma unroll
        for (int np = 0; np < 2; np++) {
            ldm_x4(bhp[np], sBh + b_off[np] + kbyte);
            ldm_x4(blp[np], sBl + b_off[np] + kbyte);
        }
#pragma unroll
        for (int mt = 0; mt < 2; mt++)
#pragma unroll
            for (int nt = 0; nt < 4; nt++) {
                const int np = nt >> 1, ix = (nt & 1) * 2;
                mma_bf16(acc[mt][nt], ah[mt],  &bhp[np][ix]);
                mma_bf16(acc[mt][nt], ah[mt],  &blp[np][ix]);
                mma_bf16(acc[mt][nt], alr[mt], &bhp[np][ix]);
            }
    }

    // stage accs to smem
    __syncthreads();
    float* Sacc = (float*)smbuf;
#pragma unroll
    for (int mt = 0; mt < 2; mt++)
#pragma unroll
        for (int nt = 0; nt < 4; nt++) {
            int r = wm * 32 + mt * 16 + g;
            int pc = wn * 32 + nt * 8 + 2 * tg;
            *(float2*)&Sacc[r * 132 + pc]       = make_float2(acc[mt][nt][0], acc[mt][nt][1]);
            *(float2*)&Sacc[(r + 8) * 132 + pc] = make_float2(acc[mt][nt][2], acc[mt][nt][3]);
        }
    __syncthreads();

    // epilogue: 4 consecutive lanes per edge; 4 float4 atomics per thread
    const float* pdp = &g_xprojd[(size_t)d * 128];
    const float* psp = &g_xprojs[(size_t)s * 128];
#pragma unroll
    for (int i = 0; i < 4; i++) {
        int c = i * 32 + q4 * 8;
        float4 pd0 = *(const float4*)&pdp[c];
        float4 pd1 = *(const float4*)&pdp[c + 4];
        float4 ps0 = *(const float4*)&psp[c];
        float4 ps1 = *(const float4*)&psp[c + 4];
        float4 sa0 = *(const float4*)&Sacc[e_loc * 132 + c];
        float4 sa1 = *(const float4*)&Sacc[e_loc * 132 + c + 4];
        float4 o;
        o.x = msg_f(sa0.x + pd0.x + ps0.x, sa0.y + pd0.y + ps0.y);
        o.y = msg_f(sa0.z + pd0.z + ps0.z, sa0.w + pd0.w + ps0.w);
        o.z = msg_f(sa1.x + pd1.x + ps1.x, sa1.y + pd1.y + ps1.y);
        o.w = msg_f(sa1.z + pd1.z + ps1.z, sa1.w + pd1.w + ps1.w);
        atomicAdd((float4*)&g_agg[(size_t)d * 64 + i * 16 + q4 * 4], o);
    }
}

// ---------------- BN statistics ----------------------------------------------
__global__ __launch_bounds__(256) void bn_stats_kernel()
{
    const int tid = threadIdx.x;
    const int c = tid & 63;
    const int rl = tid >> 6;
    float s = 0.f, s2 = 0.f;
    for (int r = blockIdx.x * 4 + rl; r < NN; r += gridDim.x * 4) {
        float v = g_agg[r * 64 + c];
        s += v; s2 += v * v;
    }
    __shared__ float sh[512];
    sh[tid] = s; sh[256 + tid] = s2;
    __syncthreads();
    if (tid < 64) {
        float ts = sh[tid] + sh[tid + 64] + sh[tid + 128] + sh[tid + 192];
        float t2 = sh[256 + tid] + sh[256 + tid + 64] + sh[256 + tid + 128] + sh[256 + tid + 192];
        atomicAdd(&g_stats[tid], (double)ts);
        atomicAdd(&g_stats[64 + tid], (double)t2);
    }
}

// ---------------- BN apply + residual, vectorized (+ emit bf16 planes) -------
__global__ __launch_bounds__(256) void bn_apply_kernel(
    const float* __restrict__ gamma, const float* __restrict__ beta, int l)
{
    __shared__ float sc[64], sf[64];
    const int tid = threadIdx.x;
    if (tid < 64) {
        double mu = g_stats[tid] * (1.0 / NN);
        double var = g_stats[64 + tid] * (1.0 / NN) - mu * mu;
        float rstd = rsqrtf((float)var + BN_EPS);
        float s = rstd * gamma[l * 64 + tid];
        sc[tid] = s;
        sf[tid] = beta[l * 64 + tid] - (float)mu * s;
    }
    __syncthreads();

    int idx = blockIdx.x * 256 + tid;
    if (idx >= NN * 16) return;
    int r = idx >> 4, c = (idx & 15) * 4;
    size_t base = (size_t)r * 64 + c;
    float4 a = *(const float4*)&g_agg[base];
    float4 x = *(const float4*)&g_x[base];
    float4 nx;
    nx.x = x.x + a.x * sc[c + 0] + sf[c + 0];
    nx.y = x.y + a.y * sc[c + 1] + sf[c + 1];
    nx.z = x.z + a.z * sc[c + 2] + sf[c + 2];
    nx.w = x.w + a.w * sc[c + 3] + sf[c + 3];
    *(float4*)&g_x[base] = nx;
    __nv_bfloat16 h0, l0, h1, l1, h2, l2, h3, l3;
    split_bf16(nx.x, h0, l0); split_bf16(nx.y, h1, l1);
    split_bf16(nx.z, h2, l2); split_bf16(nx.w, h3, l3);
    *(__nv_bfloat162*)&g_x_h[base]     = __halves2bfloat162(h0, h1);
    *(__nv_bfloat162*)&g_x_h[base + 2] = __halves2bfloat162(h2, h3);
    *(__nv_bfloat162*)&g_x_l[base]     = __halves2bfloat162(l0, l1);
    *(__nv_bfloat162*)&g_x_l[base + 2] = __halves2bfloat162(l2, l3);
}

// ---------------- zeroing ----------------------------------------------------
__global__ void zero_pool_kernel()
{
    int idx = blockIdx.x * 256 + threadIdx.x;
    if (idx < GG * 64) g_pool[idx] = 0.f;
    if (idx < GG) g_cnt[idx] = 0.f;
}

// ---------------- global mean pool (vectorized) -------------------------------
__global__ __launch_bounds__(256) void pool_kernel(const int* __restrict__ batch)
{
    int idx = blockIdx.x * 256 + threadIdx.x;
    if (idx >= NN * 16) return;
    int r = idx >> 4, cs = (idx & 15) * 4;
    float4 v = *(const float4*)&g_y[(size_t)r * 64 + cs];
    int g = batch[r];
    atomicAdd((float4*)&g_pool[g * 64 + cs], v);
    if ((idx & 15) == 0) atomicAdd(&g_cnt[g], 1.f);
}

// ---------------- dense head -------------------------------------------------
__global__ __launch_bounds__(64) void head_kernel(
    const float* __restrict__ hw, const float* __restrict__ hb,
    const float* __restrict__ ow, const float* __restrict__ ob,
    float* __restrict__ out)
{
    __shared__ float v[64];
    __shared__ float red[64];
    const int g = blockIdx.x, c = threadIdx.x;
    v[c] = g_pool[g * 64 + c] / fmaxf(g_cnt[g], 1.f);
    __syncthreads();
#pragma unroll
    for (int j = 0; j < 2; j++) {
        float acc = hb[j * 64 + c];
        const float* W = hw + j * 4096;
#pragma unroll 8
        for (int k = 0; k < 64; k++) acc += v[k] * W[k * 64 + c];
        __syncthreads();
        v[c] = fmaxf(acc, 0.f);
        __syncthreads();
    }
    red[c] = v[c] * ow[c];
    __syncthreads();
    if (c < 32) {
        float t = red[c] + red[c + 32];
#pragma unroll
        for (int off = 16; off > 0; off >>= 1)
            t += __shfl_down_sync(0xffffffffu, t, off);
        if (c == 0) out[g] = t + ob[0];
    }
}

// ---------------- launch -----------------------------------------------------
extern "C" void kernel_launch(void* const* d_in, const int* in_sizes, int n_in,
                              void* d_out, int out_size)
{
    const float* x_in  = (const float*)d_in[0];
    const int*   eidx  = (const int*)  d_in[1];
    const float* eattr = (const float*)d_in[2];
    const int*   batch = (const int*)  d_in[3];
    const float* pnw = (const float*)d_in[4];
    const float* pnb = (const float*)d_in[5];
    const float* pew = (const float*)d_in[6];
    const float* peb = (const float*)d_in[7];
    const float* smw = (const float*)d_in[8];
    const float* smb = (const float*)d_in[9];
    const float* cvw = (const float*)d_in[10];
    const float* cvb = (const float*)d_in[11];
    const float* gam = (const float*)d_in[12];
    const float* bet = (const float*)d_in[13];
    const float* ppw = (const float*)d_in[14];
    const float* ppb = (const float*)d_in[15];
    const float* hw  = (const float*)d_in[16];
    const float* hb  = (const float*)d_in[17];
    const float* ow  = (const float*)d_in[18];
    const float* ob  = (const float*)d_in[19];
    float* out = (float*)d_out;

    float* p_x; cudaGetSymbolAddress((void**)&p_x, g_x);
    float* p_y; cudaGetSymbolAddress((void**)&p_y, g_y);

    const int NODE_BLOCKS = (NN + 63) / 64;          // 782
    const int EDGE_BLOCKS = EE / 64;                 // 12500
    const int VEC_BLOCKS  = (NN * 16 + 255) / 256;   // 3125
    const int MMA_SMEM = (2 * 64 * TP + 2 * 128 * TP) * 2;   // 55296

    cudaFuncSetAttribute(edge_conv_kernel,
                         cudaFuncAttributeMaxDynamicSharedMemorySize, MMA_SMEM);
    cudaFuncSetAttribute(node_proj_kernel,
                         cudaFuncAttributeMaxDynamicSharedMemorySize, MMA_SMEM);

    // pre-conv embeds + weight split prep
    embed_kernel<IN_F, IN_F + 1, true><<<NODE_BLOCKS, 256>>>(x_in, pnw, pnb, p_x, NN);
    embed_edge_kernel<<<EDGE_BLOCKS, 256>>>(eattr, pew, peb);
    prep_wsplit_kernel<<<(LL * 3 * 8192 + 255) / 256, 256>>>(smw, cvw);

    // message-passing layers (node_proj also zeroes g_agg/g_stats)
    for (int l = 0; l < LL; l++) {
        node_proj_kernel<<<NODE_BLOCKS, 256, MMA_SMEM>>>(smb, cvb, l);
        edge_conv_kernel<<<EDGE_BLOCKS, 256, MMA_SMEM>>>(eidx, l);
        bn_stats_kernel<<<128, 256>>>();
        bn_apply_kernel<<<VEC_BLOCKS, 256>>>(gam, bet, l);
    }

    // head
    embed_kernel<HH, HH + 1, false><<<NODE_BLOCKS, 256>>>(p_x, ppw, ppb, p_y, NN);
    zero_pool_kernel<<<(GG * 64 + 255) / 256, 256>>>();
    pool_kernel<<<VEC_BLOCKS, 256>>>(batch);
    head_kernel<<<GG, 64>>>(hw, hb, ow, ob, out);
}